// round 7
// baseline (speedup 1.0000x reference)
#include <cuda_runtime.h>
#include <cstdint>

#define Bn 16
#define Tn 512
#define En 2048
#define Hn 1024
#define Dn 128

// ---------------- scratch (device globals; no allocs allowed) ----------------
__device__ float g_xw[(size_t)Bn * Tn * Hn];          // 32 MB: x@W_ih^T + biases
// Padded h exchange: slice c (8 floats = rows 8c..8c+7) lives at its own 512B
// stride -> 64KB footprint/slot -> spreads across ~64-128 L2 slices instead of
// ~8 for a dense 4KB array (the R2-R6 invariant bottleneck: 512KB/step of
// broadcast reads queueing on 8 slices ~= 1900 cyc/step).
__device__ __align__(128) float4 g_hp[2][128][32];    // 2 slots x 128 slices x 512B
__device__ unsigned int g_ctrs[4 * 128];              // 4 warp-counters, 512B apart
__device__ float g_hs[Bn * Hn];                       // per-batch final hidden

// ---------------- init: must reset per launch (graph replays) ----------------
__global__ void init_kernel() {
    int tid = blockIdx.x * blockDim.x + threadIdx.x;
    if (tid < 2 * 128 * 32) ((float4*)g_hp)[tid] = make_float4(0.f, 0.f, 0.f, 0.f);
    if (tid < 4 * 128) g_ctrs[tid] = 0u;
}

// ---------------- xW GEMM: C[8192,1024] = X[8192,2048] @ W_ih^T + (b_ih+b_hh) -
#define BM 128
#define BN 128
#define BK 16
#define SP 132   // padded smem row stride (floats)

__global__ __launch_bounds__(256, 2) void xw_gemm(
    const float* __restrict__ X, const float* __restrict__ Wih,
    const float* __restrict__ bih, const float* __restrict__ bhh,
    const int* __restrict__ lengths)
{
    const int m0 = blockIdx.x * BM;
    const int n0 = blockIdx.y * BN;
    const int b  = m0 / Tn;         // BM=128 divides Tn=512: tile stays inside one batch row
    const int t0 = m0 % Tn;
    if (t0 >= lengths[b]) return;   // fully-padded tile: its xw is never read

    __shared__ __align__(16) float As[BK * SP];
    __shared__ __align__(16) float Bs[BK * SP];

    const int tid = threadIdx.x;
    const int tx = tid & 15;
    const int ty = tid >> 4;

    float acc[8][8];
#pragma unroll
    for (int i = 0; i < 8; i++)
#pragma unroll
        for (int j = 0; j < 8; j++) acc[i][j] = 0.0f;

    for (int k0 = 0; k0 < En; k0 += BK) {
#pragma unroll
        for (int i = 0; i < 2; i++) {
            int idx = tid + i * 256;
            int m   = idx >> 2;
            int kq  = (idx & 3) << 2;
            float4 av = *(const float4*)&X  [(size_t)(m0 + m) * En + k0 + kq];
            float4 bv = *(const float4*)&Wih[(size_t)(n0 + m) * En + k0 + kq];
            As[(kq + 0) * SP + m] = av.x; As[(kq + 1) * SP + m] = av.y;
            As[(kq + 2) * SP + m] = av.z; As[(kq + 3) * SP + m] = av.w;
            Bs[(kq + 0) * SP + m] = bv.x; Bs[(kq + 1) * SP + m] = bv.y;
            Bs[(kq + 2) * SP + m] = bv.z; Bs[(kq + 3) * SP + m] = bv.w;
        }
        __syncthreads();
#pragma unroll
        for (int k = 0; k < BK; k++) {
            float4 a0 = *(const float4*)&As[k * SP + 4 * ty];
            float4 a1 = *(const float4*)&As[k * SP + 64 + 4 * ty];
            float4 b0 = *(const float4*)&Bs[k * SP + 4 * tx];
            float4 b1 = *(const float4*)&Bs[k * SP + 64 + 4 * tx];
            float ar[8] = {a0.x, a0.y, a0.z, a0.w, a1.x, a1.y, a1.z, a1.w};
            float br[8] = {b0.x, b0.y, b0.z, b0.w, b1.x, b1.y, b1.z, b1.w};
#pragma unroll
            for (int i = 0; i < 8; i++)
#pragma unroll
                for (int j = 0; j < 8; j++)
                    acc[i][j] = fmaf(ar[i], br[j], acc[i][j]);
        }
        __syncthreads();
    }

    float4 bi0 = *(const float4*)&bih[n0 + 4 * tx];
    float4 bh0 = *(const float4*)&bhh[n0 + 4 * tx];
    float4 bi1 = *(const float4*)&bih[n0 + 64 + 4 * tx];
    float4 bh1 = *(const float4*)&bhh[n0 + 64 + 4 * tx];
    float4 c0 = make_float4(bi0.x + bh0.x, bi0.y + bh0.y, bi0.z + bh0.z, bi0.w + bh0.w);
    float4 c1 = make_float4(bi1.x + bh1.x, bi1.y + bh1.y, bi1.z + bh1.z, bi1.w + bh1.w);
#pragma unroll
    for (int i = 0; i < 8; i++) {
        int m = m0 + ((i < 4) ? (4 * ty + i) : (64 + 4 * ty + i - 4));
        float4 o0 = make_float4(acc[i][0] + c0.x, acc[i][1] + c0.y,
                                acc[i][2] + c0.z, acc[i][3] + c0.w);
        float4 o1 = make_float4(acc[i][4] + c1.x, acc[i][5] + c1.y,
                                acc[i][6] + c1.z, acc[i][7] + c1.w);
        *(float4*)&g_xw[(size_t)m * Hn + n0 + 4 * tx]      = o0;
        *(float4*)&g_xw[(size_t)m * Hn + n0 + 64 + 4 * tx] = o1;
    }
}

// ---------------- fast accurate-enough tanh -----------------------------------
// tanh(x) = 1 - 2/(e^{2x}+1). __expf (EX2-based) rel err ~1e-6; cancellation
// near 0 leaves ~6e-8 ABSOLUTE error, same class as fp32 rounding. Handles
// +/-inf saturation correctly (e=inf -> 1; e=0 -> -1). ~60cy vs ~180 for tanhf.
__device__ __forceinline__ float ftanh(float x) {
    float e = __expf(2.0f * x);
    return 1.0f - __fdividef(2.0f, e + 1.0f);
}

// ---------------- sequential recurrence ---------------------------------------
// 128 CTAs (co-resident), 128 threads. CTA c owns rows [8c,8c+8) of W_hh in
// REGISTERS (warp w -> rows 2w,2w+1; lane l -> k = l+32j).
//
// Step s: read slot[(s+1)&1] (h from step s-1; zeros for s=0), write slot[s&1].
// Arrival: lane0 of warp w stores its 2 results as ONE stcg.v2 (8B) then does
// red.release.gpu.add on ctr[w] -> counter reaches 128*(s+1) when all warp-w's
// chip-wide finished step s. Poll: warp w (all lanes, same addr = 1 req) polls
// ONLY ctr[w] for >= 128*s; the single per-step __syncthreads then joins the
// four warp conditions AND the h staging -> one barrier/step.
// Safety: pass(s) => all adds(s-1) => every thread's slot reads for s-1 done
// (thread's ldcg -> STS -> bar -> lane0 add orders them) => writer at s cannot
// race readers of slot[s&1] (who were at step s-1). Release/acquire: producer
// red.release; consumer relaxed-poll + fence.acq_rel.gpu before weak ldcg.
// hsh double-buffered (s&1): stager at s (post-bar(s-1)) vs matvec reader at
// s-2 (pre-bar(s-1)) are separated by bar(s-1).
#define NBLK 128
#define RPC  8

__global__ __launch_bounds__(128, 1) void rnn_kernel(
    const float* __restrict__ Whh, const int* __restrict__ lengths)
{
    __shared__ __align__(16) float hsh[2][Hn];   // 8 KB staged h, double-buffered

    const int tid  = threadIdx.x;
    const int cta  = blockIdx.x;
    const int w    = tid >> 5;
    const int lane = tid & 31;
    const int gr0  = cta * RPC + 2 * w;   // this warp's two output rows
    const int gr1  = gr0 + 1;

    // one-time: W_hh rows into registers (coalesced: lane-stride 4B per j)
    float wr0[32], wr1[32];
#pragma unroll
    for (int j = 0; j < 32; j++) {
        wr0[j] = __ldg(&Whh[(size_t)gr0 * Hn + lane + 32 * j]);
        wr1[j] = __ldg(&Whh[(size_t)gr1 * Hn + lane + 32 * j]);
    }

    unsigned int* myctr = &g_ctrs[w * 128];

    unsigned int step = 0;
    for (int b = 0; b < Bn; b++) {
        const int L = __ldg(&lengths[b]);
        const float* xwb = g_xw + (size_t)b * Tn * Hn;
        for (int t = 0; t < L; t++) {
            // prefetch xw for this warp's rows (independent of h; overlaps poll)
            float2 xwv = make_float2(0.f, 0.f);
            if (lane == 0)
                xwv = __ldcg((const float2*)&xwb[(size_t)t * Hn + gr0]);

            // ---- poll own warp-counter: all warp-w's done with step-1 ----
            const unsigned int tgt = 128u * step;
            unsigned int v;
            do {
                asm volatile("ld.relaxed.gpu.global.u32 %0, [%1];"
                             : "=r"(v) : "l"(myctr) : "memory");
            } while (v < tgt);
            asm volatile("fence.acq_rel.gpu;" ::: "memory");

            // ---- gather slice tid (32B from its padded 512B slot) ----
            const float4* sp = &g_hp[(step + 1) & 1u][tid][0];
            float4 ha = __ldcg(sp);
            float4 hb = __ldcg(sp + 1);
            float* hcur = hsh[step & 1u];
            ((float4*)&hcur[8 * tid])[0] = ha;
            ((float4*)&hcur[8 * tid])[1] = hb;
            __syncthreads();   // joins 4 poll conditions + staging

            // ---- matvec from registers: 64 FMA + 32 conflict-free LDS.32 ----
            float a0 = 0.f, a1 = 0.f, b0 = 0.f, b1 = 0.f;
#pragma unroll
            for (int j = 0; j < 32; j += 2) {
                float hA = hcur[lane + 32 * j];
                float hB = hcur[lane + 32 * (j + 1)];
                a0 = fmaf(hA, wr0[j],     a0);
                b0 = fmaf(hA, wr1[j],     b0);
                a1 = fmaf(hB, wr0[j + 1], a1);
                b1 = fmaf(hB, wr1[j + 1], b1);
            }
            float sA = a0 + a1;
            float sB = b0 + b1;
#pragma unroll
            for (int off = 16; off > 0; off >>= 1) {
                sA += __shfl_xor_sync(0xffffffffu, sA, off);
                sB += __shfl_xor_sync(0xffffffffu, sB, off);
            }

            // lane0 finishes both rows: tanh x2, ONE 8B store, ONE release-add
            if (lane == 0) {
                float h0 = ftanh(xwv.x + sA);
                float h1 = ftanh(xwv.y + sB);
                float* sb = (float*)g_hp[step & 1u][cta];
                __stcg((float2*)&sb[2 * w], make_float2(h0, h1));
                if (t == L - 1)
                    __stcg((float2*)&g_hs[b * Hn + gr0], make_float2(h0, h1));
                asm volatile("red.release.gpu.global.add.u32 [%0], %1;"
                             :: "l"(myctr), "r"(1u) : "memory");
            }
            step++;
        }
    }
}

// ---------------- head: out[16,128] = hs @ W_l1^T + b_l1 ----------------------
__global__ void head_kernel(const float* __restrict__ Wl1,
                            const float* __restrict__ bl1,
                            float* __restrict__ out)
{
    const int b = blockIdx.x;
    const int d = threadIdx.x;   // 128
    __shared__ float hsh[Hn];
    for (int i = d; i < Hn; i += Dn) hsh[i] = g_hs[b * Hn + i];
    __syncthreads();

    float acc = bl1[d];
    const float* wr = Wl1 + (size_t)d * Hn;
#pragma unroll 4
    for (int k = 0; k < Hn; k += 4) {
        float4 wv = *(const float4*)&wr[k];
        acc = fmaf(wv.x, hsh[k + 0], acc);
        acc = fmaf(wv.y, hsh[k + 1], acc);
        acc = fmaf(wv.z, hsh[k + 2], acc);
        acc = fmaf(wv.w, hsh[k + 3], acc);
    }
    out[b * Dn + d] = acc;
}

// ---------------- launch ------------------------------------------------------
extern "C" void kernel_launch(void* const* d_in, const int* in_sizes, int n_in,
                              void* d_out, int out_size)
{
    const float* x       = (const float*)d_in[0];
    const int*   lengths = (const int*)  d_in[1];
    const float* W_ih    = (const float*)d_in[2];
    const float* W_hh    = (const float*)d_in[3];
    const float* b_ih    = (const float*)d_in[4];
    const float* b_hh    = (const float*)d_in[5];
    const float* W_l1    = (const float*)d_in[6];
    const float* b_l1    = (const float*)d_in[7];
    float* out = (float*)d_out;

    init_kernel<<<32, 256>>>();

    dim3 grid(Bn * Tn / BM, Hn / BN);
    xw_gemm<<<grid, 256>>>(x, W_ih, b_ih, b_hh, lengths);

    rnn_kernel<<<NBLK, 128>>>(W_hh, lengths);

    head_kernel<<<Bn, Dn>>>(W_l1, b_l1, out);
}